// round 1
// baseline (speedup 1.0000x reference)
#include <cuda_runtime.h>
#include <cuda_bf16.h>
#include <math.h>

// Problem constants
// B=4, N=512, D=1024, H=16, HD=64, HID=4096, RP_HID=64
// tokens M = 2048

#define EPI_STORE   0
#define EPI_BIAS    1
#define EPI_SCORES  2
#define EPI_GELU    3
#define EPI_RESGATE 4

// ---------------- scratch (device globals; allocation-free) ----------------
__device__ float g_mod[4 * 6144];                 // adaLN modulation
__device__ float g_xn[2048 * 1024];               // LN output (reused for both LNs)
__device__ float g_qkv[2048 * 3072];              // qkv
__device__ float g_att[4 * 16 * 512 * 512];       // bias -> scores -> probs (in place)
__device__ float g_ao[2048 * 1024];               // attention out (pre-proj)
__device__ float g_x1[2048 * 1024];               // residual after attention
__device__ float g_h[2048 * 4096];                // MLP hidden

// ---------------- adaLN: mod = silu(t_emb) @ w_ada^T + b_ada ----------------
__global__ __launch_bounds__(256) void ada_kernel(
    const float* __restrict__ t_emb, const float* __restrict__ w_ada,
    const float* __restrict__ b_ada, float* __restrict__ mod)
{
    __shared__ float sh[4096];
    int tid = threadIdx.x;
    for (int i = tid; i < 4096; i += 256) {
        float t = t_emb[i];
        sh[i] = t / (1.0f + __expf(-t));
    }
    __syncthreads();
    int j = blockIdx.x * 8 + (tid >> 5);
    int lane = tid & 31;
    const float* wr = w_ada + (size_t)j * 1024;
    float a0 = 0.f, a1 = 0.f, a2 = 0.f, a3 = 0.f;
    for (int k = lane; k < 1024; k += 32) {
        float w = wr[k];
        a0 = fmaf(w, sh[k], a0);
        a1 = fmaf(w, sh[1024 + k], a1);
        a2 = fmaf(w, sh[2048 + k], a2);
        a3 = fmaf(w, sh[3072 + k], a3);
    }
    for (int o = 16; o; o >>= 1) {
        a0 += __shfl_xor_sync(0xffffffffu, a0, o);
        a1 += __shfl_xor_sync(0xffffffffu, a1, o);
        a2 += __shfl_xor_sync(0xffffffffu, a2, o);
        a3 += __shfl_xor_sync(0xffffffffu, a3, o);
    }
    if (lane == 0) {
        float bb = b_ada[j];
        mod[j]              = a0 + bb;
        mod[6144 + j]       = a1 + bb;
        mod[2 * 6144 + j]   = a2 + bb;
        mod[3 * 6144 + j]   = a3 + bb;
    }
}

// ---------------- LN + adaLN modulation ----------------
// out = LN(x)*(1 + mod[b][scale_chunk]) + mod[b][shift_chunk]
__global__ __launch_bounds__(256) void ln_mod_kernel(
    const float* __restrict__ xin, const float* __restrict__ gamma,
    const float* __restrict__ beta, const float* __restrict__ mod,
    int shift_chunk, int scale_chunk, float* __restrict__ out)
{
    int token = blockIdx.x;
    int b = token >> 9;
    int tid = threadIdx.x;
    const float* xr = xin + (size_t)token * 1024;
    float v[4];
    float s = 0.f, sq = 0.f;
#pragma unroll
    for (int i = 0; i < 4; i++) {
        float t = xr[i * 256 + tid];
        v[i] = t;
        s += t;
        sq += t * t;
    }
    for (int o = 16; o; o >>= 1) {
        s  += __shfl_xor_sync(0xffffffffu, s, o);
        sq += __shfl_xor_sync(0xffffffffu, sq, o);
    }
    __shared__ float ss[8], ssq[8], smu, srstd;
    int wid = tid >> 5, lane = tid & 31;
    if (lane == 0) { ss[wid] = s; ssq[wid] = sq; }
    __syncthreads();
    if (tid == 0) {
        float S = 0.f, Q = 0.f;
        for (int i = 0; i < 8; i++) { S += ss[i]; Q += ssq[i]; }
        float mu = S * (1.0f / 1024.0f);
        float var = Q * (1.0f / 1024.0f) - mu * mu;
        smu = mu;
        srstd = rsqrtf(var + 1e-5f);
    }
    __syncthreads();
    float mu = smu, rstd = srstd;
    const float* modb = mod + (size_t)b * 6144;
    const float* shm = modb + shift_chunk * 1024;
    const float* scm = modb + scale_chunk * 1024;
    float* outr = out + (size_t)token * 1024;
#pragma unroll
    for (int i = 0; i < 4; i++) {
        int c = i * 256 + tid;
        float ln = (v[i] - mu) * rstd * gamma[c] + beta[c];
        outr[c] = ln * (1.0f + scm[c]) + shm[c];
    }
}

// ---------------- rel-pos bias MLP, fused per (b,i,j) ----------------
// writes bias into g_att laid out [B][H][N][N]
__global__ __launch_bounds__(256) void relpos_kernel(
    const float* __restrict__ rel, const float* __restrict__ w1,
    const float* __restrict__ b1, const float* __restrict__ w2,
    const float* __restrict__ b2, float* __restrict__ out)
{
    __shared__ float sw1[128], sb1[64], sw2[1024], sb2[16];
    int tid = threadIdx.x;
    if (tid < 128) sw1[tid] = w1[tid];
    if (tid < 64)  sb1[tid] = b1[tid];
    for (int i = tid; i < 1024; i += 256) sw2[i] = w2[i];
    if (tid < 16)  sb2[tid] = b2[tid];
    __syncthreads();

    int gid = blockIdx.x * 256 + tid;  // (b*512 + i)*512 + j, < 1048576
    float r0 = rel[2 * (size_t)gid];
    float r1 = rel[2 * (size_t)gid + 1];
    float h[64];
#pragma unroll
    for (int u = 0; u < 64; u++)
        h[u] = fmaxf(fmaf(sw1[2 * u], r0, fmaf(sw1[2 * u + 1], r1, sb1[u])), 0.0f);
    int b = gid >> 18;
    int rem = gid & 262143;
    size_t base = ((size_t)b << 22) + (size_t)rem;
#pragma unroll
    for (int hh = 0; hh < 16; hh++) {
        float s2 = sb2[hh];
#pragma unroll
        for (int u = 0; u < 64; u++)
            s2 = fmaf(h[u], sw2[hh * 64 + u], s2);
        out[base + ((size_t)hh << 18)] = s2;
    }
}

// ---------------- masked row softmax over 512, in place ----------------
__global__ __launch_bounds__(256) void softmax_kernel(float* __restrict__ att)
{
    int row = blockIdx.x * 8 + (threadIdx.x >> 5);
    int lane = threadIdx.x & 31;
    float* p = att + (size_t)row * 512;
    float ev[16];
    float mx = -3.4e38f;
#pragma unroll
    for (int i = 0; i < 16; i++) {
        ev[i] = p[i * 32 + lane];
        mx = fmaxf(mx, ev[i]);
    }
    for (int o = 16; o; o >>= 1) mx = fmaxf(mx, __shfl_xor_sync(0xffffffffu, mx, o));
    float sum = 0.f;
#pragma unroll
    for (int i = 0; i < 16; i++) {
        ev[i] = __expf(ev[i] - mx);
        sum += ev[i];
    }
    for (int o = 16; o; o >>= 1) sum += __shfl_xor_sync(0xffffffffu, sum, o);
    float inv = 1.0f / sum;
#pragma unroll
    for (int i = 0; i < 16; i++) p[i * 32 + lane] = ev[i] * inv;
}

// ---------------- generic register-blocked fp32 GEMM ----------------
// C[m,n] = sum_k A[m,k] * B(n,k)   (BNT=true:  B is [N,K], NT layout)
//                                  (BNT=false: B is [K,N], NN layout)
// batched over blockIdx.z with z = zb*zdiv + zh and per-(zb,zh) pointer strides.
template<int BM, int BN, int BK, int TM, int TN, int EPI, bool BNT>
__global__ __launch_bounds__(256) void gemm_kernel(
    const float* __restrict__ A, int lda, long long sAb, long long sAh,
    const float* __restrict__ B, int ldb, long long sBb, long long sBh,
    float* __restrict__ C, int ldc, long long sCb, long long sCh,
    int M, int N, int K, int zdiv,
    const float* __restrict__ bias, const float* __restrict__ res,
    const float* __restrict__ gatebase, const int* __restrict__ maskp,
    float alpha)
{
    constexpr int TX = BN / TN;  // threads along n
    // TX * (BM/TM) == 256
    __shared__ __align__(16) float As[BK][BM + 4];
    __shared__ __align__(16) float Bs[BK][BN + 4];

    int z = blockIdx.z;
    int zb = z / zdiv;
    int zh = z - zb * zdiv;
    A += zb * sAb + zh * sAh;
    B += zb * sBb + zh * sBh;
    C += zb * sCb + zh * sCh;

    int tid = threadIdx.x;
    int tx = tid % TX;
    int ty = tid / TX;
    int m0 = blockIdx.y * BM;
    int n0 = blockIdx.x * BN;

    float acc[TM][TN];
#pragma unroll
    for (int i = 0; i < TM; i++)
#pragma unroll
        for (int j = 0; j < TN; j++) acc[i][j] = 0.0f;

    for (int k0 = 0; k0 < K; k0 += BK) {
#pragma unroll
        for (int i = tid; i < BM * BK; i += 256) {
            int m = i / BK, k = i % BK;
            As[k][m] = A[(long long)(m0 + m) * lda + (k0 + k)];
        }
        if (BNT) {
#pragma unroll
            for (int i = tid; i < BN * BK; i += 256) {
                int n = i / BK, k = i % BK;
                Bs[k][n] = B[(long long)(n0 + n) * ldb + (k0 + k)];
            }
        } else {
#pragma unroll
            for (int i = tid; i < BN * BK; i += 256) {
                int k = i / BN, n = i % BN;
                Bs[k][n] = B[(long long)(k0 + k) * ldb + (n0 + n)];
            }
        }
        __syncthreads();
#pragma unroll
        for (int k = 0; k < BK; k++) {
            float a[TM], bf[TN];
#pragma unroll
            for (int i = 0; i < TM; i += 4) {
                float4 t = *reinterpret_cast<const float4*>(&As[k][ty * TM + i]);
                a[i] = t.x; a[i + 1] = t.y; a[i + 2] = t.z; a[i + 3] = t.w;
            }
#pragma unroll
            for (int j = 0; j < TN; j += 4) {
                float4 t = *reinterpret_cast<const float4*>(&Bs[k][tx * TN + j]);
                bf[j] = t.x; bf[j + 1] = t.y; bf[j + 2] = t.z; bf[j + 3] = t.w;
            }
#pragma unroll
            for (int i = 0; i < TM; i++)
#pragma unroll
                for (int j = 0; j < TN; j++)
                    acc[i][j] = fmaf(a[i], bf[j], acc[i][j]);
        }
        __syncthreads();
    }

#pragma unroll
    for (int i = 0; i < TM; i++) {
        int gm = m0 + ty * TM + i;
#pragma unroll
        for (int j = 0; j < TN; j++) {
            int gn = n0 + tx * TN + j;
            long long idx = (long long)gm * ldc + gn;
            float v = acc[i][j];
            if constexpr (EPI == EPI_STORE) {
                C[idx] = v;
            } else if constexpr (EPI == EPI_BIAS) {
                C[idx] = v + bias[gn];
            } else if constexpr (EPI == EPI_SCORES) {
                v = v * alpha + C[idx];  // C preloaded with rel-pos bias
                if (maskp[(long long)zb * N + gn] == 0) v = -1e30f;
                C[idx] = v;
            } else if constexpr (EPI == EPI_GELU) {
                v += bias[gn];
                C[idx] = 0.5f * v * (1.0f + erff(v * 0.70710678118654752f));
            } else {  // EPI_RESGATE
                v += bias[gn];
                float gt = gatebase[(gm >> 9) * 6144 + gn];  // per-batch gate
                C[idx] = res[idx] + gt * v;
            }
        }
    }
}

// ---------------- launcher ----------------
extern "C" void kernel_launch(void* const* d_in, const int* in_sizes, int n_in,
                              void* d_out, int out_size)
{
    const float* x      = (const float*)d_in[0];
    const float* t_emb  = (const float*)d_in[1];
    const float* rel    = (const float*)d_in[2];
    const int*   amask  = (const int*)d_in[3];
    const float* w_ada  = (const float*)d_in[4];
    const float* b_ada  = (const float*)d_in[5];
    const float* g1     = (const float*)d_in[6];
    const float* be1    = (const float*)d_in[7];
    const float* g2     = (const float*)d_in[8];
    const float* be2    = (const float*)d_in[9];
    const float* w_qkv  = (const float*)d_in[10];
    const float* b_qkv  = (const float*)d_in[11];
    const float* w_proj = (const float*)d_in[12];
    const float* b_proj = (const float*)d_in[13];
    const float* w_rp1  = (const float*)d_in[14];
    const float* b_rp1  = (const float*)d_in[15];
    const float* w_rp2  = (const float*)d_in[16];
    const float* b_rp2  = (const float*)d_in[17];
    const float* w_fc1  = (const float*)d_in[18];
    const float* b_fc1  = (const float*)d_in[19];
    const float* w_fc2  = (const float*)d_in[20];
    const float* b_fc2  = (const float*)d_in[21];
    float* out = (float*)d_out;

    float *mod, *xn, *qkv, *att, *ao, *x1, *hb;
    cudaGetSymbolAddress((void**)&mod, g_mod);
    cudaGetSymbolAddress((void**)&xn,  g_xn);
    cudaGetSymbolAddress((void**)&qkv, g_qkv);
    cudaGetSymbolAddress((void**)&att, g_att);
    cudaGetSymbolAddress((void**)&ao,  g_ao);
    cudaGetSymbolAddress((void**)&x1,  g_x1);
    cudaGetSymbolAddress((void**)&hb,  g_h);

    // 1. adaLN modulation
    ada_kernel<<<768, 256>>>(t_emb, w_ada, b_ada, mod);
    // 2. LN1 + modulate
    ln_mod_kernel<<<2048, 256>>>(x, g1, be1, mod, 0, 1, xn);
    // 3. qkv = xn @ w_qkv^T + b_qkv        [2048,3072] = [2048,1024]x[3072,1024]^T
    gemm_kernel<128, 128, 16, 8, 8, EPI_BIAS, true><<<dim3(24, 16, 1), 256>>>(
        xn, 1024, 0, 0, w_qkv, 1024, 0, 0, qkv, 3072, 0, 0,
        2048, 3072, 1024, 1, b_qkv, nullptr, nullptr, nullptr, 0.f);
    // 4. rel-pos bias -> g_att [B][H][N][N]
    relpos_kernel<<<4096, 256>>>(rel, w_rp1, b_rp1, w_rp2, b_rp2, att);
    // 5. scores = q k^T / 8 + bias, masked (batched over b,h)
    gemm_kernel<128, 128, 16, 8, 8, EPI_SCORES, true><<<dim3(4, 4, 64), 256>>>(
        qkv, 3072, 512LL * 3072, 64,
        qkv + 1024, 3072, 512LL * 3072, 64,
        att, 512, 1LL << 22, 1LL << 18,
        512, 512, 64, 16, nullptr, nullptr, nullptr, amask, 0.125f);
    // 6. softmax in place
    softmax_kernel<<<4096, 256>>>(att);
    // 7. O = P @ V (NN)  -> g_ao [token][h*64+d]
    gemm_kernel<128, 64, 16, 8, 4, EPI_STORE, false><<<dim3(1, 4, 64), 256>>>(
        att, 512, 1LL << 22, 1LL << 18,
        qkv + 2048, 3072, 512LL * 3072, 64,
        ao, 1024, 512LL * 1024, 64,
        512, 64, 512, 16, nullptr, nullptr, nullptr, nullptr, 0.f);
    // 8. x1 = x + gate_s * (ao @ w_proj^T + b_proj)
    gemm_kernel<128, 64, 16, 8, 4, EPI_RESGATE, true><<<dim3(16, 16, 1), 256>>>(
        ao, 1024, 0, 0, w_proj, 1024, 0, 0, x1, 1024, 0, 0,
        2048, 1024, 1024, 1, b_proj, x, mod + 2048, nullptr, 0.f);
    // 9. LN2 + modulate
    ln_mod_kernel<<<2048, 256>>>(x1, g2, be2, mod, 3, 4, xn);
    // 10. h = gelu(xn @ w_fc1^T + b_fc1)
    gemm_kernel<128, 128, 16, 8, 8, EPI_GELU, true><<<dim3(32, 16, 1), 256>>>(
        xn, 1024, 0, 0, w_fc1, 1024, 0, 0, hb, 4096, 0, 0,
        2048, 4096, 1024, 1, b_fc1, nullptr, nullptr, nullptr, 0.f);
    // 11. out = x1 + gate_m * (h @ w_fc2^T + b_fc2)
    gemm_kernel<128, 64, 16, 8, 4, EPI_RESGATE, true><<<dim3(16, 16, 1), 256>>>(
        hb, 4096, 0, 0, w_fc2, 4096, 0, 0, out, 1024, 0, 0,
        2048, 1024, 4096, 1, b_fc2, x1, mod + 5120, nullptr, 0.f);
}

// round 6
// speedup vs baseline: 1.4426x; 1.4426x over previous
#include <cuda_runtime.h>
#include <cuda_bf16.h>
#include <math.h>
#include <stdint.h>

// B=4, N=512, D=1024, H=16, HD=64, HID=4096, RP_HID=64; tokens M=2048

#define EPI_STORE   0
#define EPI_SCORES  2

#define TEPI_BIAS    0
#define TEPI_GELUP   1
#define TEPI_RESGATE 2

// ---------------- scratch ----------------
__device__ float g_mod[4 * 6144];
__device__ float g_qkv[2048 * 3072];
__device__ float g_att[4 * 16 * 512 * 512];
__device__ float g_ao[2048 * 1024];
__device__ float g_x1[2048 * 1024];
__device__ __nv_bfloat16 g_xnh[2048 * 1024], g_xnl[2048 * 1024];
__device__ __nv_bfloat16 g_aoh[2048 * 1024], g_aol[2048 * 1024];
__device__ __nv_bfloat16 g_hh[2048 * 4096], g_hl[2048 * 4096];
__device__ __nv_bfloat16 g_wqkvh[3072 * 1024], g_wqkvl[3072 * 1024];
__device__ __nv_bfloat16 g_wprojh[1024 * 1024], g_wprojl[1024 * 1024];
__device__ __nv_bfloat16 g_wfc1h[4096 * 1024], g_wfc1l[4096 * 1024];
__device__ __nv_bfloat16 g_wfc2h[1024 * 4096], g_wfc2l[1024 * 4096];

// ---------------- helpers ----------------
__device__ __forceinline__ uint32_t smem_u32(const void* p) {
    uint32_t a;
    asm("{ .reg .u64 t; cvta.to.shared.u64 t, %1; cvt.u32.u64 %0, t; }" : "=r"(a) : "l"(p));
    return a;
}
__device__ __forceinline__ void cp16(uint32_t s, const void* g) {
    asm volatile("cp.async.cg.shared.global [%0], [%1], 16;" :: "r"(s), "l"(g));
}
__device__ __forceinline__ void cp_commit() {
    asm volatile("cp.async.commit_group;" ::: "memory");
}
__device__ __forceinline__ void cp_wait0() {
    asm volatile("cp.async.wait_group 0;" ::: "memory");
}
__device__ __forceinline__ void ldmat4(uint32_t& r0, uint32_t& r1, uint32_t& r2, uint32_t& r3, uint32_t a) {
    asm volatile("ldmatrix.sync.aligned.m8n8.x4.shared.b16 {%0,%1,%2,%3}, [%4];"
                 : "=r"(r0), "=r"(r1), "=r"(r2), "=r"(r3) : "r"(a));
}
__device__ __forceinline__ void mma16816(float* c, const uint32_t* a, uint32_t b0, uint32_t b1) {
    asm volatile(
        "mma.sync.aligned.m16n8k16.row.col.f32.bf16.bf16.f32 "
        "{%0,%1,%2,%3}, {%4,%5,%6,%7}, {%8,%9}, {%0,%1,%2,%3};"
        : "+f"(c[0]), "+f"(c[1]), "+f"(c[2]), "+f"(c[3])
        : "r"(a[0]), "r"(a[1]), "r"(a[2]), "r"(a[3]), "r"(b0), "r"(b1));
}

// ---------------- adaLN ----------------
__global__ __launch_bounds__(256) void ada_kernel(
    const float* __restrict__ t_emb, const float* __restrict__ w_ada,
    const float* __restrict__ b_ada, float* __restrict__ mod)
{
    __shared__ float sh[4096];
    int tid = threadIdx.x;
    for (int i = tid; i < 4096; i += 256) {
        float t = t_emb[i];
        sh[i] = t / (1.0f + __expf(-t));
    }
    __syncthreads();
    int j = blockIdx.x * 8 + (tid >> 5);
    int lane = tid & 31;
    const float* wr = w_ada + (size_t)j * 1024;
    float a0 = 0.f, a1 = 0.f, a2 = 0.f, a3 = 0.f;
    for (int k = lane; k < 1024; k += 32) {
        float w = wr[k];
        a0 = fmaf(w, sh[k], a0);
        a1 = fmaf(w, sh[1024 + k], a1);
        a2 = fmaf(w, sh[2048 + k], a2);
        a3 = fmaf(w, sh[3072 + k], a3);
    }
    for (int o = 16; o; o >>= 1) {
        a0 += __shfl_xor_sync(0xffffffffu, a0, o);
        a1 += __shfl_xor_sync(0xffffffffu, a1, o);
        a2 += __shfl_xor_sync(0xffffffffu, a2, o);
        a3 += __shfl_xor_sync(0xffffffffu, a3, o);
    }
    if (lane == 0) {
        float bb = b_ada[j];
        mod[j]            = a0 + bb;
        mod[6144 + j]     = a1 + bb;
        mod[2 * 6144 + j] = a2 + bb;
        mod[3 * 6144 + j] = a3 + bb;
    }
}

// ---------------- LN + modulation -> bf16 pair ----------------
__global__ __launch_bounds__(256) void ln_mod_kernel(
    const float* __restrict__ xin, const float* __restrict__ gamma,
    const float* __restrict__ beta, const float* __restrict__ mod,
    int shift_chunk, int scale_chunk,
    __nv_bfloat16* __restrict__ outh, __nv_bfloat16* __restrict__ outl)
{
    int token = blockIdx.x;
    int b = token >> 9;
    int tid = threadIdx.x;
    const float* xr = xin + (size_t)token * 1024;
    float v[4];
    float s = 0.f, sq = 0.f;
#pragma unroll
    for (int i = 0; i < 4; i++) {
        float t = xr[i * 256 + tid];
        v[i] = t; s += t; sq += t * t;
    }
    for (int o = 16; o; o >>= 1) {
        s  += __shfl_xor_sync(0xffffffffu, s, o);
        sq += __shfl_xor_sync(0xffffffffu, sq, o);
    }
    __shared__ float ss[8], ssq[8], smu, srstd;
    int wid = tid >> 5, lane = tid & 31;
    if (lane == 0) { ss[wid] = s; ssq[wid] = sq; }
    __syncthreads();
    if (tid == 0) {
        float S = 0.f, Q = 0.f;
        for (int i = 0; i < 8; i++) { S += ss[i]; Q += ssq[i]; }
        float mu = S * (1.0f / 1024.0f);
        float var = Q * (1.0f / 1024.0f) - mu * mu;
        smu = mu; srstd = rsqrtf(var + 1e-5f);
    }
    __syncthreads();
    float mu = smu, rstd = srstd;
    const float* modb = mod + (size_t)b * 6144;
    const float* shm = modb + shift_chunk * 1024;
    const float* scm = modb + scale_chunk * 1024;
    size_t rb = (size_t)token * 1024;
#pragma unroll
    for (int i = 0; i < 4; i++) {
        int c = i * 256 + tid;
        float ln = (v[i] - mu) * rstd * gamma[c] + beta[c];
        float o = ln * (1.0f + scm[c]) + shm[c];
        __nv_bfloat16 h = __float2bfloat16(o);
        outh[rb + c] = h;
        outl[rb + c] = __float2bfloat16(o - __bfloat162float(h));
    }
}

// ---------------- split fp32 -> bf16 pair ----------------
__global__ __launch_bounds__(256) void split_kernel(
    const float* __restrict__ src, __nv_bfloat16* __restrict__ hi,
    __nv_bfloat16* __restrict__ lo, int n4)
{
    int i = blockIdx.x * 256 + threadIdx.x;
    if (i >= n4) return;
    float4 v = reinterpret_cast<const float4*>(src)[i];
    __nv_bfloat16 h0 = __float2bfloat16(v.x), h1 = __float2bfloat16(v.y);
    __nv_bfloat16 h2 = __float2bfloat16(v.z), h3 = __float2bfloat16(v.w);
    __nv_bfloat162 H0; H0.x = h0; H0.y = h1;
    __nv_bfloat162 H1; H1.x = h2; H1.y = h3;
    __nv_bfloat162 L0, L1;
    L0.x = __float2bfloat16(v.x - __bfloat162float(h0));
    L0.y = __float2bfloat16(v.y - __bfloat162float(h1));
    L1.x = __float2bfloat16(v.z - __bfloat162float(h2));
    L1.y = __float2bfloat16(v.w - __bfloat162float(h3));
    reinterpret_cast<__nv_bfloat162*>(hi)[2 * i]     = H0;
    reinterpret_cast<__nv_bfloat162*>(hi)[2 * i + 1] = H1;
    reinterpret_cast<__nv_bfloat162*>(lo)[2 * i]     = L0;
    reinterpret_cast<__nv_bfloat162*>(lo)[2 * i + 1] = L1;
}

// ---------------- rel-pos bias MLP ----------------
__global__ __launch_bounds__(256) void relpos_kernel(
    const float* __restrict__ rel, const float* __restrict__ w1,
    const float* __restrict__ b1, const float* __restrict__ w2,
    const float* __restrict__ b2, float* __restrict__ out)
{
    __shared__ float sw1[128], sb1[64], sw2[1024], sb2[16];
    int tid = threadIdx.x;
    if (tid < 128) sw1[tid] = w1[tid];
    if (tid < 64)  sb1[tid] = b1[tid];
    for (int i = tid; i < 1024; i += 256) sw2[i] = w2[i];
    if (tid < 16)  sb2[tid] = b2[tid];
    __syncthreads();
    int gid = blockIdx.x * 256 + tid;
    float r0 = rel[2 * (size_t)gid];
    float r1 = rel[2 * (size_t)gid + 1];
    float h[64];
#pragma unroll
    for (int u = 0; u < 64; u++)
        h[u] = fmaxf(fmaf(sw1[2 * u], r0, fmaf(sw1[2 * u + 1], r1, sb1[u])), 0.0f);
    int b = gid >> 18;
    int rem = gid & 262143;
    size_t base = ((size_t)b << 22) + (size_t)rem;
#pragma unroll
    for (int hh = 0; hh < 16; hh++) {
        float s2 = sb2[hh];
#pragma unroll
        for (int u = 0; u < 64; u++)
            s2 = fmaf(h[u], sw2[hh * 64 + u], s2);
        out[base + ((size_t)hh << 18)] = s2;
    }
}

// ---------------- softmax ----------------
__global__ __launch_bounds__(256) void softmax_kernel(float* __restrict__ att)
{
    int row = blockIdx.x * 8 + (threadIdx.x >> 5);
    int lane = threadIdx.x & 31;
    float* p = att + (size_t)row * 512;
    float ev[16];
    float mx = -3.4e38f;
#pragma unroll
    for (int i = 0; i < 16; i++) { ev[i] = p[i * 32 + lane]; mx = fmaxf(mx, ev[i]); }
    for (int o = 16; o; o >>= 1) mx = fmaxf(mx, __shfl_xor_sync(0xffffffffu, mx, o));
    float sum = 0.f;
#pragma unroll
    for (int i = 0; i < 16; i++) { ev[i] = __expf(ev[i] - mx); sum += ev[i]; }
    for (int o = 16; o; o >>= 1) sum += __shfl_xor_sync(0xffffffffu, sum, o);
    float inv = 1.0f / sum;
#pragma unroll
    for (int i = 0; i < 16; i++) p[i * 32 + lane] = ev[i] * inv;
}

// ---------------- SIMT fp32 GEMM (attention only) ----------------
template<int BM, int BN, int BK, int TM, int TN, int EPI, bool BNT>
__global__ __launch_bounds__(256) void gemm_kernel(
    const float* __restrict__ A, int lda, long long sAb, long long sAh,
    const float* __restrict__ B, int ldb, long long sBb, long long sBh,
    float* __restrict__ C, int ldc, long long sCb, long long sCh,
    int M, int N, int K, int zdiv,
    const int* __restrict__ maskp, float alpha)
{
    constexpr int TX = BN / TN;
    __shared__ __align__(16) float As[BK][BM + 4];
    __shared__ __align__(16) float Bs[BK][BN + 4];
    int z = blockIdx.z;
    int zb = z / zdiv;
    int zh = z - zb * zdiv;
    A += zb * sAb + zh * sAh;
    B += zb * sBb + zh * sBh;
    C += zb * sCb + zh * sCh;
    int tid = threadIdx.x;
    int tx = tid % TX;
    int ty = tid / TX;
    int m0 = blockIdx.y * BM;
    int n0 = blockIdx.x * BN;
    float acc[TM][TN];
#pragma unroll
    for (int i = 0; i < TM; i++)
#pragma unroll
        for (int j = 0; j < TN; j++) acc[i][j] = 0.0f;
    for (int k0 = 0; k0 < K; k0 += BK) {
#pragma unroll
        for (int i = tid; i < BM * BK; i += 256) {
            int m = i / BK, k = i % BK;
            As[k][m] = A[(long long)(m0 + m) * lda + (k0 + k)];
        }
        if (BNT) {
#pragma unroll
            for (int i = tid; i < BN * BK; i += 256) {
                int n = i / BK, k = i % BK;
                Bs[k][n] = B[(long long)(n0 + n) * ldb + (k0 + k)];
            }
        } else {
#pragma unroll
            for (int i = tid; i < BN * BK; i += 256) {
                int k = i / BN, n = i % BN;
                Bs[k][n] = B[(long long)(k0 + k) * ldb + (n0 + n)];
            }
        }
        __syncthreads();
#pragma unroll
        for (int k = 0; k < BK; k++) {
            float a[TM], bf[TN];
#pragma unroll
            for (int i = 0; i < TM; i += 4) {
                float4 t = *reinterpret_cast<const float4*>(&As[k][ty * TM + i]);
                a[i] = t.x; a[i + 1] = t.y; a[i + 2] = t.z; a[i + 3] = t.w;
            }
#pragma unroll
            for (int j = 0; j < TN; j += 4) {
                float4 t = *reinterpret_cast<const float4*>(&Bs[k][tx * TN + j]);
                bf[j] = t.x; bf[j + 1] = t.y; bf[j + 2] = t.z; bf[j + 3] = t.w;
            }
#pragma unroll
            for (int i = 0; i < TM; i++)
#pragma unroll
                for (int j = 0; j < TN; j++)
                    acc[i][j] = fmaf(a[i], bf[j], acc[i][j]);
        }
        __syncthreads();
    }
#pragma unroll
    for (int i = 0; i < TM; i++) {
        int gm = m0 + ty * TM + i;
#pragma unroll
        for (int j = 0; j < TN; j++) {
            int gn = n0 + tx * TN + j;
            long long idx = (long long)gm * ldc + gn;
            float v = acc[i][j];
            if constexpr (EPI == EPI_STORE) {
                C[idx] = v;
            } else {  // EPI_SCORES
                v = v * alpha + C[idx];
                if (maskp[(long long)zb * N + gn] == 0) v = -1e30f;
                C[idx] = v;
            }
        }
    }
}

// ---------------- HMMA bf16x3 GEMM: C[M,N] = A[M,K] @ B[N,K]^T ----------------
// CTA 128x128, BK=32, 8 warps of 32x64; K' = 3K with source select
// smem: stage s at s*20480: A tile [128][pitch 80B], B tile at +10240
// epilogue reuses smem as float [128][132]
static constexpr int HG_SMEM = 128 * 132 * 4;  // 67584 >= 2*20480

template<int EPI>
__global__ __launch_bounds__(256) void hmma_gemm(
    const __nv_bfloat16* __restrict__ Ah, const __nv_bfloat16* __restrict__ Al, int lda,
    const __nv_bfloat16* __restrict__ Bh, const __nv_bfloat16* __restrict__ Bl, int ldb,
    float* __restrict__ C, int ldc, int K,
    const float* __restrict__ bias, const float* __restrict__ res,
    const float* __restrict__ gate,
    __nv_bfloat16* __restrict__ outh, __nv_bfloat16* __restrict__ outl)
{
    extern __shared__ char smem[];
    uint32_t sbase = smem_u32(smem);
    int tid = threadIdx.x;
    int m0 = blockIdx.y * 128;
    int n0 = blockIdx.x * 128;

    int w = tid >> 5;
    int lane = tid & 31;
    int wm0 = (w & 3) * 32;
    int wn0 = (w >> 2) * 64;
    int mm = lane >> 3, rr = lane & 7;
    // ldmatrix per-thread row/byte offsets
    int aRowOff = wm0 + ((mm & 1) << 3) + rr;
    int aByte   = (mm >> 1) << 4;
    int bRowOff = wn0 + ((mm >> 1) << 3) + rr;
    int bByte   = (mm & 1) << 4;

    float acc[2][8][4];
#pragma unroll
    for (int mi = 0; mi < 2; mi++)
#pragma unroll
        for (int ni = 0; ni < 8; ni++)
#pragma unroll
            for (int q = 0; q < 4; q++) acc[mi][ni][q] = 0.0f;

    int nc = (3 * K) >> 5;

    // copy mapping: per thread 2 A-chunks + 2 B-chunks (chunk-major for bank phases)
    auto load_chunk = [&](int c, int s) {
        int kk = c << 5;
        int blk = (kk >= K) + (kk >= 2 * K);
        int koff = kk - blk * K;
        const __nv_bfloat16* pA = (blk == 1) ? Al : Ah;
        const __nv_bfloat16* pB = (blk == 2) ? Bl : Bh;
        uint32_t sA = sbase + s * 20480;
        uint32_t sB = sA + 10240;
#pragma unroll
        for (int u = 0; u < 2; u++) {
            int i = u * 256 + tid;        // i = ch*128 + r
            int ch = i >> 7, r = i & 127;
            cp16(sA + r * 80 + ch * 16, pA + (size_t)(m0 + r) * lda + koff + ch * 8);
            cp16(sB + r * 80 + ch * 16, pB + (size_t)(n0 + r) * ldb + koff + ch * 8);
        }
        cp_commit();
    };

    load_chunk(0, 0);
    for (int c = 0; c < nc; c++) {
        int s = c & 1;
        cp_wait0();
        __syncthreads();
        if (c + 1 < nc) load_chunk(c + 1, s ^ 1);
        uint32_t sA = sbase + s * 20480;
        uint32_t sB = sA + 10240;
#pragma unroll
        for (int ks = 0; ks < 2; ks++) {
            uint32_t af[2][4];
            ldmat4(af[0][0], af[0][1], af[0][2], af[0][3],
                   sA + (uint32_t)(aRowOff) * 80 + ks * 32 + aByte);
            ldmat4(af[1][0], af[1][1], af[1][2], af[1][3],
                   sA + (uint32_t)(aRowOff + 16) * 80 + ks * 32 + aByte);
            uint32_t bfr[4][4];
#pragma unroll
            for (int bi = 0; bi < 4; bi++)
                ldmat4(bfr[bi][0], bfr[bi][1], bfr[bi][2], bfr[bi][3],
                       sB + (uint32_t)(bRowOff + bi * 16) * 80 + ks * 32 + bByte);
#pragma unroll
            for (int mi = 0; mi < 2; mi++)
#pragma unroll
                for (int ni = 0; ni < 8; ni++) {
                    int bi = ni >> 1, hb = (ni & 1) * 2;
                    mma16816(acc[mi][ni], af[mi], bfr[bi][hb], bfr[bi][hb + 1]);
                }
        }
        __syncthreads();
    }

    // stage accumulators into smem [128][132]
    float* sC = reinterpret_cast<float*>(smem);
    int g = lane >> 2, tg = lane & 3;
#pragma unroll
    for (int mi = 0; mi < 2; mi++)
#pragma unroll
        for (int ni = 0; ni < 8; ni++) {
            int r0 = wm0 + mi * 16 + g;
            int c0 = wn0 + ni * 8 + tg * 2;
            sC[r0 * 132 + c0]           = acc[mi][ni][0];
            sC[r0 * 132 + c0 + 1]       = acc[mi][ni][1];
            sC[(r0 + 8) * 132 + c0]     = acc[mi][ni][2];
            sC[(r0 + 8) * 132 + c0 + 1] = acc[mi][ni][3];
        }
    __syncthreads();

    // coalesced fused epilogue
    for (int i = tid; i < 16384; i += 256) {
        int row = i >> 7, col = i & 127;
        int gm = m0 + row, gn = n0 + col;
        float v = sC[row * 132 + col];
        size_t idx = (size_t)gm * ldc + gn;
        if constexpr (EPI == TEPI_BIAS) {
            C[idx] = v + bias[gn];
        } else if constexpr (EPI == TEPI_GELUP) {
            v += bias[gn];
            float gl = 0.5f * v * (1.0f + erff(v * 0.70710678118654752f));
            __nv_bfloat16 h = __float2bfloat16(gl);
            outh[idx] = h;
            outl[idx] = __float2bfloat16(gl - __bfloat162float(h));
        } else {
            v += bias[gn];
            float gt = gate[(gm >> 9) * 6144 + gn];
            C[idx] = res[idx] + gt * v;
        }
    }
}

// ---------------- launcher ----------------
extern "C" void kernel_launch(void* const* d_in, const int* in_sizes, int n_in,
                              void* d_out, int out_size)
{
    const float* x      = (const float*)d_in[0];
    const float* t_emb  = (const float*)d_in[1];
    const float* rel    = (const float*)d_in[2];
    const int*   amask  = (const int*)d_in[3];
    const float* w_ada  = (const float*)d_in[4];
    const float* b_ada  = (const float*)d_in[5];
    const float* g1     = (const float*)d_in[6];
    const float* be1    = (const float*)d_in[7];
    const float* g2     = (const float*)d_in[8];
    const float* be2    = (const float*)d_in[9];
    const float* w_qkv  = (const float*)d_in[10];
    const float* b_qkv  = (const float*)d_in[11];
    const float* w_proj = (const float*)d_in[12];
    const float* b_proj = (const float*)d_in[13];
    const float* w_rp1  = (const float*)d_in[14];
    const float* b_rp1  = (const float*)d_in[15];
    const float* w_rp2  = (const float*)d_in[16];
    const float* b_rp2  = (const float*)d_in[17];
    const float* w_fc1  = (const float*)d_in[18];
    const float* b_fc1  = (const float*)d_in[19];
    const float* w_fc2  = (const float*)d_in[20];
    const float* b_fc2  = (const float*)d_in[21];
    float* out = (float*)d_out;

    float *mod, *qkv, *att, *ao, *x1;
    __nv_bfloat16 *xnh, *xnl, *aoh, *aol, *hh, *hl;
    __nv_bfloat16 *wqkvh, *wqkvl, *wprojh, *wprojl, *wfc1h, *wfc1l, *wfc2h, *wfc2l;
    cudaGetSymbolAddress((void**)&mod, g_mod);
    cudaGetSymbolAddress((void**)&qkv, g_qkv);
    cudaGetSymbolAddress((void**)&att, g_att);
    cudaGetSymbolAddress((void**)&ao,  g_ao);
    cudaGetSymbolAddress((void**)&x1,  g_x1);
    cudaGetSymbolAddress((void**)&xnh, g_xnh);
    cudaGetSymbolAddress((void**)&xnl, g_xnl);
    cudaGetSymbolAddress((void**)&aoh, g_aoh);
    cudaGetSymbolAddress((void**)&aol, g_aol);
    cudaGetSymbolAddress((void**)&hh,  g_hh);
    cudaGetSymbolAddress((void**)&hl,  g_hl);
    cudaGetSymbolAddress((void**)&wqkvh, g_wqkvh);
    cudaGetSymbolAddress((void**)&wqkvl, g_wqkvl);
    cudaGetSymbolAddress((void**)&wprojh, g_wprojh);
    cudaGetSymbolAddress((void**)&wprojl, g_wprojl);
    cudaGetSymbolAddress((void**)&wfc1h, g_wfc1h);
    cudaGetSymbolAddress((void**)&wfc1l, g_wfc1l);
    cudaGetSymbolAddress((void**)&wfc2h, g_wfc2h);
    cudaGetSymbolAddress((void**)&wfc2l, g_wfc2l);

    cudaFuncSetAttribute(hmma_gemm<TEPI_BIAS>,    cudaFuncAttributeMaxDynamicSharedMemorySize, HG_SMEM);
    cudaFuncSetAttribute(hmma_gemm<TEPI_GELUP>,   cudaFuncAttributeMaxDynamicSharedMemorySize, HG_SMEM);
    cudaFuncSetAttribute(hmma_gemm<TEPI_RESGATE>, cudaFuncAttributeMaxDynamicSharedMemorySize, HG_SMEM);

    // weight splits
    split_kernel<<<3072, 256>>>(w_qkv,  wqkvh,  wqkvl,  3072 * 1024 / 4);
    split_kernel<<<1024, 256>>>(w_proj, wprojh, wprojl, 1024 * 1024 / 4);
    split_kernel<<<4096, 256>>>(w_fc1,  wfc1h,  wfc1l,  4096 * 1024 / 4);
    split_kernel<<<4096, 256>>>(w_fc2,  wfc2h,  wfc2l,  4096 * 1024 / 4);

    // 1. adaLN modulation
    ada_kernel<<<768, 256>>>(t_emb, w_ada, b_ada, mod);
    // 2. LN1 + modulate -> bf16 pair
    ln_mod_kernel<<<2048, 256>>>(x, g1, be1, mod, 0, 1, xnh, xnl);
    // 3. qkv (HMMA)
    hmma_gemm<TEPI_BIAS><<<dim3(24, 16), 256, HG_SMEM>>>(
        xnh, xnl, 1024, wqkvh, wqkvl, 1024, qkv, 3072, 1024,
        b_qkv, nullptr, nullptr, nullptr, nullptr);
    // 4. rel-pos bias
    relpos_kernel<<<4096, 256>>>(rel, w_rp1, b_rp1, w_rp2, b_rp2, att);
    // 5. scores = q k^T / 8 + bias, masked (SIMT)
    gemm_kernel<128, 128, 16, 8, 8, EPI_SCORES, true><<<dim3(4, 4, 64), 256>>>(
        qkv, 3072, 512LL * 3072, 64,
        qkv + 1024, 3072, 512LL * 3072, 64,
        att, 512, 1LL << 22, 1LL << 18,
        512, 512, 64, 16, amask, 0.125f);
    // 6. softmax
    softmax_kernel<<<4096, 256>>>(att);
    // 7. O = P @ V (SIMT)
    gemm_kernel<128, 64, 16, 8, 4, EPI_STORE, false><<<dim3(1, 4, 64), 256>>>(
        att, 512, 1LL << 22, 1LL << 18,
        qkv + 2048, 3072, 512LL * 3072, 64,
        ao, 1024, 512LL * 1024, 64,
        512, 64, 512, 16, nullptr, 0.f);
    // 8. split ao
    split_kernel<<<2048, 256>>>(ao, aoh, aol, 2048 * 1024 / 4);
    // 9. proj + gated residual (HMMA)
    hmma_gemm<TEPI_RESGATE><<<dim3(8, 16), 256, HG_SMEM>>>(
        aoh, aol, 1024, wprojh, wprojl, 1024, x1, 1024, 1024,
        b_proj, x, mod + 2048, nullptr, nullptr);
    // 10. LN2 + modulate -> bf16 pair
    ln_mod_kernel<<<2048, 256>>>(x1, g2, be2, mod, 3, 4, xnh, xnl);
    // 11. fc1 + gelu -> bf16 pair (HMMA)
    hmma_gemm<TEPI_GELUP><<<dim3(32, 16), 256, HG_SMEM>>>(
        xnh, xnl, 1024, wfc1h, wfc1l, 1024, nullptr, 4096, 1024,
        b_fc1, nullptr, nullptr, hh, hl);
    // 12. fc2 + gated residual (HMMA)
    hmma_gemm<TEPI_RESGATE><<<dim3(8, 16), 256, HG_SMEM>>>(
        hh, hl, 4096, wfc2h, wfc2l, 4096, out, 1024, 4096,
        b_fc2, x1, mod + 5120, nullptr, nullptr);
}